// round 1
// baseline (speedup 1.0000x reference)
#include <cuda_runtime.h>
#include <math.h>

#define BATCH 512
#define NEG   (-1e9f)

// ---------------- scratch (no allocations allowed) ----------------
__device__ float g_a1[BATCH * 32 * 15 * 15];   // after stage1 pool
__device__ float g_a2[BATCH * 32 * 6 * 6];     // after stage2 pool
__device__ float g_feat[BATCH * 128];          // after stage3 pool (=feat)
__device__ float g_exh[3 * 128];               // emb @ Wxh
__device__ int   g_ops[BATCH * 8 * 3];         // chosen op sequence per (b,beam)

// ---------------- stage 1: conv1(1->32,3x3) + BN + ReLU + pool ----------------
__global__ void k_conv1(const float* __restrict__ x,
                        const float* __restrict__ w, const float* __restrict__ cb,
                        const float* __restrict__ g, const float* __restrict__ bb,
                        const float* __restrict__ m, const float* __restrict__ v)
{
    __shared__ float sin[32 * 32];
    __shared__ float sw[32 * 9];
    __shared__ float sscale[32], sshift[32];
    int b = blockIdx.x, tid = threadIdx.x;
    const float* xin = x + b * 1024;
    for (int i = tid; i < 1024; i += 256) sin[i] = xin[i];
    for (int i = tid; i < 288;  i += 256) sw[i]  = w[i];
    if (tid < 32) {
        float inv = g[tid] * rsqrtf(v[tid] + 1e-5f);
        sscale[tid] = inv;
        sshift[tid] = bb[tid] - m[tid] * inv + cb[tid] * inv;
    }
    __syncthreads();
    // 32 channels * 15*15 pooled outputs
    for (int i = tid; i < 32 * 225; i += 256) {
        int c = i / 225, p = i % 225, py = p / 15, px = p % 15;
        const float* wc = sw + c * 9;
        const float* ip = sin + (2 * py) * 32 + 2 * px;
        float s00 = 0.f, s01 = 0.f, s10 = 0.f, s11 = 0.f;
        #pragma unroll
        for (int ky = 0; ky < 3; ky++)
            #pragma unroll
            for (int kx = 0; kx < 3; kx++) {
                float wv = wc[ky * 3 + kx];
                s00 += ip[ky * 32 + kx]           * wv;
                s01 += ip[ky * 32 + kx + 1]       * wv;
                s10 += ip[(ky + 1) * 32 + kx]     * wv;
                s11 += ip[(ky + 1) * 32 + kx + 1] * wv;
            }
        float sc = sscale[c], sh = sshift[c];
        float acc = fmaxf(s00 * sc + sh, 0.f) + fmaxf(s01 * sc + sh, 0.f)
                  + fmaxf(s10 * sc + sh, 0.f) + fmaxf(s11 * sc + sh, 0.f);
        g_a1[(b * 32 + c) * 225 + p] = acc * 0.25f;
    }
}

// ---------------- stage 2: conv2(32->32,3x3) + BN + ReLU + pool ----------------
// grid (512, 2): blockIdx.y selects 16 output channels
__global__ void k_conv2(const float* __restrict__ w, const float* __restrict__ cb,
                        const float* __restrict__ g, const float* __restrict__ bb,
                        const float* __restrict__ m, const float* __restrict__ v)
{
    __shared__ float sin[32 * 225];    // 28.8 KB
    __shared__ float sw[16 * 32 * 9];  // 18 KB
    __shared__ float sscale[16], sshift[16];
    int b = blockIdx.x, by = blockIdx.y, tid = threadIdx.x;
    const float* ain = g_a1 + b * (32 * 225);
    for (int i = tid; i < 32 * 225; i += 256) sin[i] = ain[i];
    for (int i = tid; i < 4608;     i += 256) sw[i]  = w[by * 4608 + i];
    if (tid < 16) {
        int c = by * 16 + tid;
        float inv = g[c] * rsqrtf(v[c] + 1e-5f);
        sscale[tid] = inv;
        sshift[tid] = bb[c] - m[c] * inv + cb[c] * inv;
    }
    __syncthreads();
    // 16 channels * 6*6 pooled outputs = 576
    for (int i = tid; i < 576; i += 256) {
        int ocl = i / 36, p = i % 36, py = p / 6, px = p % 6;
        float s00 = 0.f, s01 = 0.f, s10 = 0.f, s11 = 0.f;
        const float* wb = sw + ocl * (32 * 9);
        for (int ic = 0; ic < 32; ic++) {
            const float* ip = sin + ic * 225 + (2 * py) * 15 + 2 * px;
            const float* wp = wb + ic * 9;
            #pragma unroll
            for (int ky = 0; ky < 3; ky++)
                #pragma unroll
                for (int kx = 0; kx < 3; kx++) {
                    float wv = wp[ky * 3 + kx];
                    s00 += ip[ky * 15 + kx]           * wv;
                    s01 += ip[ky * 15 + kx + 1]       * wv;
                    s10 += ip[(ky + 1) * 15 + kx]     * wv;
                    s11 += ip[(ky + 1) * 15 + kx + 1] * wv;
                }
        }
        float sc = sscale[ocl], sh = sshift[ocl];
        float acc = fmaxf(s00 * sc + sh, 0.f) + fmaxf(s01 * sc + sh, 0.f)
                  + fmaxf(s10 * sc + sh, 0.f) + fmaxf(s11 * sc + sh, 0.f);
        int oc = by * 16 + ocl;
        g_a2[((b * 32 + oc) * 6 + py) * 6 + px] = acc * 0.25f;
    }
}

// ---------------- stage 3: conv3(32->32,3x3) + BN + ReLU + pool -> feat ----------------
__global__ void k_conv3(const float* __restrict__ w, const float* __restrict__ cb,
                        const float* __restrict__ g, const float* __restrict__ bb,
                        const float* __restrict__ m, const float* __restrict__ v)
{
    __shared__ float sin[32 * 36];     // 4.6 KB
    __shared__ float sw[32 * 32 * 9];  // 36 KB
    __shared__ float sscale[32], sshift[32];
    int b = blockIdx.x, tid = threadIdx.x;  // 128 threads
    const float* ain = g_a2 + b * (32 * 36);
    for (int i = tid; i < 32 * 36; i += 128) sin[i] = ain[i];
    for (int i = tid; i < 9216;    i += 128) sw[i]  = w[i];
    if (tid < 32) {
        float inv = g[tid] * rsqrtf(v[tid] + 1e-5f);
        sscale[tid] = inv;
        sshift[tid] = bb[tid] - m[tid] * inv + cb[tid] * inv;
    }
    __syncthreads();
    // 128 outputs: c = tid/4, y=(tid%4)/2, x=tid%2  -> matches reshape (c*4+y*2+x)
    int c = tid >> 2, r = tid & 3, y = r >> 1, xx = r & 1;
    float s00 = 0.f, s01 = 0.f, s10 = 0.f, s11 = 0.f;
    const float* wb = sw + c * (32 * 9);
    for (int ic = 0; ic < 32; ic++) {
        const float* ip = sin + ic * 36 + (2 * y) * 6 + 2 * xx;
        const float* wp = wb + ic * 9;
        #pragma unroll
        for (int ky = 0; ky < 3; ky++)
            #pragma unroll
            for (int kx = 0; kx < 3; kx++) {
                float wv = wp[ky * 3 + kx];
                s00 += ip[ky * 6 + kx]           * wv;
                s01 += ip[ky * 6 + kx + 1]       * wv;
                s10 += ip[(ky + 1) * 6 + kx]     * wv;
                s11 += ip[(ky + 1) * 6 + kx + 1] * wv;
            }
    }
    float sc = sscale[c], sh = sshift[c];
    float acc = fmaxf(s00 * sc + sh, 0.f) + fmaxf(s01 * sc + sh, 0.f)
              + fmaxf(s10 * sc + sh, 0.f) + fmaxf(s11 * sc + sh, 0.f);
    g_feat[b * 128 + tid] = acc * 0.25f;
}

// ---------------- exh = emb @ Wxh  (3 x 128) ----------------
__global__ void k_exh(const float* __restrict__ emb, const float* __restrict__ Wxh)
{
    int o = blockIdx.x, j = threadIdx.x;
    float acc = 0.f;
    for (int d = 0; d < 128; d++) acc += emb[o * 128 + d] * Wxh[d * 128 + j];
    g_exh[o * 128 + j] = acc;
}

// ---------------- beam search router (one block per sample) ----------------
__global__ void k_beam(const float* __restrict__ Whh, const float* __restrict__ bh,
                       const float* __restrict__ Who, const float* __restrict__ bo)
{
    __shared__ float shr[2][1024];       // [0]=current hr, [1]=gathered
    __shared__ float sWho[384], sbh[128], sexh[384], sbo[3];
    __shared__ float slog[24], stotal[24];
    __shared__ float nscore[8];
    __shared__ int   nbeam[8], nop[8];
    __shared__ float sscore[8];
    __shared__ int   sops[2][3][8];

    int b = blockIdx.x, tid = threadIdx.x;
    int warp = tid >> 5, lane = tid & 31;

    for (int i = tid; i < 384; i += 256) { sWho[i] = Who[i]; sexh[i] = g_exh[i]; }
    if (tid < 128) sbh[tid] = bh[tid];
    if (tid < 3)   sbo[tid] = bo[tid];
    for (int i = tid; i < 1024; i += 256) shr[0][i] = g_feat[b * 128 + (i & 127)];
    if (tid < 8) sscore[tid] = (tid == 0) ? 0.f : NEG;
    __syncthreads();

    int cur = 0;
    for (int t = 0; t < 3; t++) {
        // ---- logits[k][o] = hr[k] . Who[:,o] + bo[o]  (warp k) ----
        {
            const float* h = shr[0] + warp * 128;
            float a0 = 0.f, a1 = 0.f, a2 = 0.f;
            for (int d = lane; d < 128; d += 32) {
                float hv = h[d];
                a0 += hv * sWho[d * 3 + 0];
                a1 += hv * sWho[d * 3 + 1];
                a2 += hv * sWho[d * 3 + 2];
            }
            #pragma unroll
            for (int off = 16; off; off >>= 1) {
                a0 += __shfl_xor_sync(0xffffffffu, a0, off);
                a1 += __shfl_xor_sync(0xffffffffu, a1, off);
                a2 += __shfl_xor_sync(0xffffffffu, a2, off);
            }
            if (lane == 0) {
                slog[warp * 3 + 0] = a0 + sbo[0];
                slog[warp * 3 + 1] = a1 + sbo[1];
                slog[warp * 3 + 2] = a2 + sbo[2];
            }
        }
        __syncthreads();
        // ---- log_softmax(logits/0.4) + scores ----
        if (tid < 8) {
            float y0 = slog[tid * 3 + 0] * 2.5f;
            float y1 = slog[tid * 3 + 1] * 2.5f;
            float y2 = slog[tid * 3 + 2] * 2.5f;
            float mx = fmaxf(y0, fmaxf(y1, y2));
            float lse = logf(expf(y0 - mx) + expf(y1 - mx) + expf(y2 - mx));
            float sc = sscore[tid];
            stotal[tid * 3 + 0] = sc + (y0 - mx - lse);
            stotal[tid * 3 + 1] = sc + (y1 - mx - lse);
            stotal[tid * 3 + 2] = sc + (y2 - mx - lse);
        }
        __syncthreads();
        // ---- stable top-8 of 24 (lower index wins ties, like lax.top_k) ----
        if (tid < 24) {
            float v = stotal[tid];
            int rank = 0;
            #pragma unroll
            for (int j = 0; j < 24; j++) {
                float u = stotal[j];
                rank += (u > v) || (u == v && j < tid);
            }
            if (rank < 8) { nscore[rank] = v; nbeam[rank] = tid / 3; nop[rank] = tid % 3; }
        }
        __syncthreads();
        // ---- gather hr + scores + ops history ----
        for (int i = tid; i < 1024; i += 256) {
            int k = i >> 7;
            shr[1][i] = shr[0][nbeam[k] * 128 + (i & 127)];
        }
        if (tid < 8) {
            sscore[tid] = nscore[tid];
            for (int s = 0; s < t; s++) sops[1 - cur][s][tid] = sops[cur][s][nbeam[tid]];
            sops[1 - cur][t][tid] = nop[tid];
        }
        __syncthreads();
        cur ^= 1;
        // ---- hr = tanh(hr_sel @ Whh + exh[op] + bh)  (warp k, 4 cols/lane) ----
        {
            const float* h = shr[1] + warp * 128;
            float acc0 = 0.f, acc1 = 0.f, acc2 = 0.f, acc3 = 0.f;
            for (int d = 0; d < 128; d++) {
                float hv = h[d];
                const float* wr = Whh + d * 128;
                acc0 += hv * wr[lane];
                acc1 += hv * wr[lane + 32];
                acc2 += hv * wr[lane + 64];
                acc3 += hv * wr[lane + 96];
            }
            int op = nop[warp];
            const float* ex = sexh + op * 128;
            float* o = shr[0] + warp * 128;
            o[lane]      = tanhf(acc0 + ex[lane]      + sbh[lane]);
            o[lane + 32] = tanhf(acc1 + ex[lane + 32] + sbh[lane + 32]);
            o[lane + 64] = tanhf(acc2 + ex[lane + 64] + sbh[lane + 64]);
            o[lane + 96] = tanhf(acc3 + ex[lane + 96] + sbh[lane + 96]);
        }
        __syncthreads();
    }
    if (tid < 8) {
        #pragma unroll
        for (int s = 0; s < 3; s++) g_ops[(b * 8 + tid) * 3 + s] = sops[cur][s][tid];
    }
}

// ---------------- expert chain + final classifier (one block per (b,beam)) ----------------
__global__ void k_expert(const float* __restrict__ Wexp, const float* __restrict__ bexp,
                         const float* __restrict__ Wout, const float* __restrict__ bout,
                         float* __restrict__ out)
{
    __shared__ float h[128], h2[128];
    __shared__ float slog10[10];
    __shared__ float smx, slse;
    int row = blockIdx.x;          // b*8 + k
    int b = row >> 3;
    int tid = threadIdx.x;         // 128
    h[tid] = g_feat[b * 128 + tid];
    __syncthreads();
    #pragma unroll
    for (int t = 0; t < 3; t++) {
        int o = g_ops[row * 3 + t];
        const float* W = Wexp + o * (128 * 128);
        float acc = bexp[o * 128 + tid];
        for (int d = 0; d < 128; d++) acc += h[d] * W[d * 128 + tid];
        h2[tid] = fmaxf(acc, 0.f);
        __syncthreads();
        h[tid] = h2[tid];
        __syncthreads();
    }
    if (tid < 10) {
        float l = bout[tid];
        for (int d = 0; d < 128; d++) l += h[d] * Wout[d * 10 + tid];
        slog10[tid] = l;
    }
    __syncthreads();
    if (tid == 0) {
        float mx = slog10[0];
        #pragma unroll
        for (int i = 1; i < 10; i++) mx = fmaxf(mx, slog10[i]);
        float s = 0.f;
        #pragma unroll
        for (int i = 0; i < 10; i++) s += expf(slog10[i] - mx);
        smx = mx; slse = logf(s);
    }
    __syncthreads();
    if (tid < 10) out[row * 10 + tid] = slog10[tid] - smx - slse;
}

// ---------------- launcher ----------------
extern "C" void kernel_launch(void* const* d_in, const int* in_sizes, int n_in,
                              void* d_out, int out_size)
{
    const float* x       = (const float*)d_in[0];
    const float* conv1_w = (const float*)d_in[1];
    const float* conv1_b = (const float*)d_in[2];
    const float* bn1_g   = (const float*)d_in[3];
    const float* bn1_b   = (const float*)d_in[4];
    const float* bn1_m   = (const float*)d_in[5];
    const float* bn1_v   = (const float*)d_in[6];
    const float* conv2_w = (const float*)d_in[7];
    const float* conv2_b = (const float*)d_in[8];
    const float* bn2_g   = (const float*)d_in[9];
    const float* bn2_b   = (const float*)d_in[10];
    const float* bn2_m   = (const float*)d_in[11];
    const float* bn2_v   = (const float*)d_in[12];
    const float* conv3_w = (const float*)d_in[13];
    const float* conv3_b = (const float*)d_in[14];
    const float* bn3_g   = (const float*)d_in[15];
    const float* bn3_b   = (const float*)d_in[16];
    const float* bn3_m   = (const float*)d_in[17];
    const float* bn3_v   = (const float*)d_in[18];
    const float* Wxh     = (const float*)d_in[19];
    const float* Whh     = (const float*)d_in[20];
    const float* bh      = (const float*)d_in[21];
    const float* Who     = (const float*)d_in[22];
    const float* bo      = (const float*)d_in[23];
    const float* emb     = (const float*)d_in[24];
    const float* Wexp    = (const float*)d_in[25];
    const float* bexp    = (const float*)d_in[26];
    const float* Wout    = (const float*)d_in[27];
    const float* bout    = (const float*)d_in[28];
    float* out = (float*)d_out;

    k_conv1<<<BATCH, 256>>>(x, conv1_w, conv1_b, bn1_g, bn1_b, bn1_m, bn1_v);
    k_conv2<<<dim3(BATCH, 2), 256>>>(conv2_w, conv2_b, bn2_g, bn2_b, bn2_m, bn2_v);
    k_conv3<<<BATCH, 128>>>(conv3_w, conv3_b, bn3_g, bn3_b, bn3_m, bn3_v);
    k_exh<<<3, 128>>>(emb, Wxh);
    k_beam<<<BATCH, 256>>>(Whh, bh, Who, bo);
    k_expert<<<BATCH * 8, 128>>>(Wexp, bexp, Wout, bout, out);
}

// round 2
// speedup vs baseline: 3.4521x; 3.4521x over previous
#include <cuda_runtime.h>
#include <math.h>

#define BATCH 512
#define NEG   (-1e9f)

// ---------------- scratch ----------------
__device__ float g_feat[BATCH * 128];

// =====================================================================
// Fused conv1+conv2+conv3 (+BN+ReLU+pool each) per image.
// 288 threads/block, 80KB dynamic smem.
// =====================================================================
__global__ void __launch_bounds__(288, 2)
k_conv_all(const float* __restrict__ x,
           const float* __restrict__ w1, const float* __restrict__ cb1,
           const float* __restrict__ g1, const float* __restrict__ bb1,
           const float* __restrict__ m1, const float* __restrict__ v1,
           const float* __restrict__ w2, const float* __restrict__ cb2,
           const float* __restrict__ g2, const float* __restrict__ bb2,
           const float* __restrict__ m2, const float* __restrict__ v2,
           const float* __restrict__ w3, const float* __restrict__ cb3,
           const float* __restrict__ g3, const float* __restrict__ bb3,
           const float* __restrict__ m3, const float* __restrict__ v3)
{
    extern __shared__ float dsm[];
    float* sx  = dsm;               // 32 x 34 padded   = 1088
    float* sa1 = dsm + 1088;        // 32 x 15 x 18     = 8640
    float* swb = sa1 + 8640;        // 9216 ([ic][oc][k], reused w2 -> w3)
    float* sa2 = swb + 9216;        // 32 x 6 x 8       = 1536
    __shared__ float sw1[288];
    __shared__ float sc1s[32], sc1h[32], sc2s[32], sc2h[32], sc3s[32], sc3h[32];

    int b = blockIdx.x, tid = threadIdx.x;

    // ---- phase 0: stage input, w1, w2 (remapped), BN affines ----
    const float* xin = x + b * 1024;
    for (int i = tid; i < 1024; i += 288) {
        int row = i >> 5, col = i & 31;
        sx[row * 34 + col] = xin[i];
    }
    if (tid < 288) sw1[tid] = w1[tid];
    for (int i = tid; i < 9216; i += 288) {
        int oc = i / 288, rem = i - oc * 288, ic = rem / 9, k = rem - ic * 9;
        swb[(ic * 32 + oc) * 9 + k] = w2[i];
    }
    if (tid < 32) {
        float inv = g1[tid] * rsqrtf(v1[tid] + 1e-5f);
        sc1s[tid] = inv; sc1h[tid] = bb1[tid] - m1[tid] * inv + cb1[tid] * inv;
        inv = g2[tid] * rsqrtf(v2[tid] + 1e-5f);
        sc2s[tid] = inv; sc2h[tid] = bb2[tid] - m2[tid] * inv + cb2[tid] * inv;
        inv = g3[tid] * rsqrtf(v3[tid] + 1e-5f);
        sc3s[tid] = inv; sc3h[tid] = bb3[tid] - m3[tid] * inv + cb3[tid] * inv;
    }
    __syncthreads();

    // ---- conv1: 1->32, pooled out 15x15 ----
    for (int i = tid; i < 7200; i += 288) {
        int c = i / 225, p = i - c * 225, py = p / 15, px = p - py * 15;
        const float* wc = sw1 + c * 9;
        const float* ip = sx + (2 * py) * 34 + 2 * px;
        float r[4][4];
        #pragma unroll
        for (int rr = 0; rr < 4; rr++) {
            float2 a = *(const float2*)(ip + rr * 34);
            float2 q = *(const float2*)(ip + rr * 34 + 2);
            r[rr][0] = a.x; r[rr][1] = a.y; r[rr][2] = q.x; r[rr][3] = q.y;
        }
        float s00 = 0.f, s01 = 0.f, s10 = 0.f, s11 = 0.f;
        #pragma unroll
        for (int ky = 0; ky < 3; ky++)
            #pragma unroll
            for (int kx = 0; kx < 3; kx++) {
                float wv = wc[ky * 3 + kx];
                s00 += r[ky][kx]     * wv;  s01 += r[ky][kx + 1]     * wv;
                s10 += r[ky + 1][kx] * wv;  s11 += r[ky + 1][kx + 1] * wv;
            }
        float sc = sc1s[c], sh = sc1h[c];
        sa1[(c * 15 + py) * 18 + px] = 0.25f *
            (fmaxf(s00 * sc + sh, 0.f) + fmaxf(s01 * sc + sh, 0.f) +
             fmaxf(s10 * sc + sh, 0.f) + fmaxf(s11 * sc + sh, 0.f));
    }
    __syncthreads();

    // ---- conv2: 32->32, pooled out 6x6. Thread = 4 oc x 1 pooled pos ----
    {
        int ocg = tid / 36;            // 0..7
        int p = tid - ocg * 36, py = p / 6, px = p - py * 6;
        float s[4][4];
        #pragma unroll
        for (int a = 0; a < 4; a++)
            #pragma unroll
            for (int q = 0; q < 4; q++) s[a][q] = 0.f;
        for (int ic = 0; ic < 32; ic++) {
            const float* ip = sa1 + (ic * 15 + 2 * py) * 18 + 2 * px;
            float r[4][4];
            #pragma unroll
            for (int rr = 0; rr < 4; rr++) {
                float2 a = *(const float2*)(ip + rr * 18);
                float2 q = *(const float2*)(ip + rr * 18 + 2);
                r[rr][0] = a.x; r[rr][1] = a.y; r[rr][2] = q.x; r[rr][3] = q.y;
            }
            const float* wb = swb + (ic * 32 + ocg * 4) * 9;
            #pragma unroll
            for (int o4 = 0; o4 < 4; o4++) {
                const float* wp = wb + o4 * 9;
                #pragma unroll
                for (int ky = 0; ky < 3; ky++)
                    #pragma unroll
                    for (int kx = 0; kx < 3; kx++) {
                        float wv = wp[ky * 3 + kx];
                        s[o4][0] += r[ky][kx]     * wv;  s[o4][1] += r[ky][kx + 1]     * wv;
                        s[o4][2] += r[ky + 1][kx] * wv;  s[o4][3] += r[ky + 1][kx + 1] * wv;
                    }
            }
        }
        #pragma unroll
        for (int o4 = 0; o4 < 4; o4++) {
            int oc = ocg * 4 + o4;
            float sc = sc2s[oc], sh = sc2h[oc];
            sa2[(oc * 6 + py) * 8 + px] = 0.25f *
                (fmaxf(s[o4][0] * sc + sh, 0.f) + fmaxf(s[o4][1] * sc + sh, 0.f) +
                 fmaxf(s[o4][2] * sc + sh, 0.f) + fmaxf(s[o4][3] * sc + sh, 0.f));
        }
    }
    __syncthreads();

    // ---- reload swb with w3 (same [ic][oc][k] remap) ----
    for (int i = tid; i < 9216; i += 288) {
        int oc = i / 288, rem = i - oc * 288, ic = rem / 9, k = rem - ic * 9;
        swb[(ic * 32 + oc) * 9 + k] = w3[i];
    }
    __syncthreads();

    // ---- conv3: 32->32, pooled out 2x2 -> feat[128] ----
    if (tid < 128) {
        int c = tid >> 2, q = tid & 3, y = q >> 1, xx = q & 1;
        float s00 = 0.f, s01 = 0.f, s10 = 0.f, s11 = 0.f;
        for (int ic = 0; ic < 32; ic++) {
            const float* ip = sa2 + (ic * 6 + 2 * y) * 8 + 2 * xx;
            float r[4][4];
            #pragma unroll
            for (int rr = 0; rr < 4; rr++) {
                float2 a = *(const float2*)(ip + rr * 8);
                float2 qq = *(const float2*)(ip + rr * 8 + 2);
                r[rr][0] = a.x; r[rr][1] = a.y; r[rr][2] = qq.x; r[rr][3] = qq.y;
            }
            const float* wp = swb + (ic * 32 + c) * 9;
            #pragma unroll
            for (int ky = 0; ky < 3; ky++)
                #pragma unroll
                for (int kx = 0; kx < 3; kx++) {
                    float wv = wp[ky * 3 + kx];
                    s00 += r[ky][kx]     * wv;  s01 += r[ky][kx + 1]     * wv;
                    s10 += r[ky + 1][kx] * wv;  s11 += r[ky + 1][kx + 1] * wv;
                }
        }
        float sc = sc3s[c], sh = sc3h[c];
        g_feat[b * 128 + tid] = 0.25f *
            (fmaxf(s00 * sc + sh, 0.f) + fmaxf(s01 * sc + sh, 0.f) +
             fmaxf(s10 * sc + sh, 0.f) + fmaxf(s11 * sc + sh, 0.f));
    }
}

// =====================================================================
// Fused: exh + beam search + expert chain + classifier. 1 block / sample.
// =====================================================================
__global__ void __launch_bounds__(256)
k_router(const float* __restrict__ Whh, const float* __restrict__ bh,
         const float* __restrict__ Who, const float* __restrict__ bo,
         const float* __restrict__ emb, const float* __restrict__ Wxh,
         const float* __restrict__ Wexp, const float* __restrict__ bexp,
         const float* __restrict__ Wout, const float* __restrict__ bout,
         float* __restrict__ out)
{
    __shared__ float shr[2][1024];
    __shared__ float hbuf[8][128];
    __shared__ float sfeat[128];
    __shared__ float sexh[384], sWho[384], sbh[128], sbo[3];
    __shared__ float slog[24], stotal[24];
    __shared__ float nscore[8], sscore[8];
    __shared__ int   nbeam[8], nop[8], sops[2][3][8];

    int b = blockIdx.x, tid = threadIdx.x;
    int warp = tid >> 5, lane = tid & 31;

    for (int i = tid; i < 384; i += 256) sWho[i] = Who[i];
    if (tid < 128) { sbh[tid] = bh[tid]; sfeat[tid] = g_feat[b * 128 + tid]; }
    if (tid < 3)   sbo[tid] = bo[tid];
    if (tid < 8)   sscore[tid] = (tid == 0) ? 0.f : NEG;
    for (int i = tid; i < 1024; i += 256) shr[0][i] = g_feat[b * 128 + (i & 127)];
    // exh = emb @ Wxh  (3x128), per-block
    for (int i = tid; i < 384; i += 256) {
        int o = i >> 7, j = i & 127;
        float acc = 0.f;
        #pragma unroll 4
        for (int d = 0; d < 128; d++) acc += emb[o * 128 + d] * Wxh[d * 128 + j];
        sexh[i] = acc;
    }
    __syncthreads();

    int cur = 0;
    for (int t = 0; t < 3; t++) {
        // logits[k][o] = hr[k] . Who[:,o] + bo[o]   (warp k)
        {
            const float* h = shr[0] + warp * 128;
            float a0 = 0.f, a1 = 0.f, a2 = 0.f;
            for (int d = lane; d < 128; d += 32) {
                float hv = h[d];
                a0 += hv * sWho[d * 3 + 0];
                a1 += hv * sWho[d * 3 + 1];
                a2 += hv * sWho[d * 3 + 2];
            }
            #pragma unroll
            for (int off = 16; off; off >>= 1) {
                a0 += __shfl_xor_sync(0xffffffffu, a0, off);
                a1 += __shfl_xor_sync(0xffffffffu, a1, off);
                a2 += __shfl_xor_sync(0xffffffffu, a2, off);
            }
            if (lane == 0) {
                slog[warp * 3 + 0] = a0 + sbo[0];
                slog[warp * 3 + 1] = a1 + sbo[1];
                slog[warp * 3 + 2] = a2 + sbo[2];
            }
        }
        __syncthreads();
        // log_softmax(logits/0.4) + scores
        if (tid < 8) {
            float y0 = slog[tid * 3 + 0] * 2.5f;
            float y1 = slog[tid * 3 + 1] * 2.5f;
            float y2 = slog[tid * 3 + 2] * 2.5f;
            float mx = fmaxf(y0, fmaxf(y1, y2));
            float lse = logf(expf(y0 - mx) + expf(y1 - mx) + expf(y2 - mx));
            float sc = sscore[tid];
            stotal[tid * 3 + 0] = sc + (y0 - mx - lse);
            stotal[tid * 3 + 1] = sc + (y1 - mx - lse);
            stotal[tid * 3 + 2] = sc + (y2 - mx - lse);
        }
        __syncthreads();
        // stable top-8 of 24 (lower index wins ties == lax.top_k)
        if (tid < 24) {
            float v = stotal[tid];
            int rank = 0;
            #pragma unroll
            for (int j = 0; j < 24; j++) {
                float u = stotal[j];
                rank += (u > v) || (u == v && j < tid);
            }
            if (rank < 8) { nscore[rank] = v; nbeam[rank] = tid / 3; nop[rank] = tid % 3; }
        }
        __syncthreads();
        // gather hr + scores + ops history
        for (int i = tid; i < 1024; i += 256) {
            int k = i >> 7;
            shr[1][i] = shr[0][nbeam[k] * 128 + (i & 127)];
        }
        if (tid < 8) {
            sscore[tid] = nscore[tid];
            for (int s = 0; s < t; s++) sops[1 - cur][s][tid] = sops[cur][s][nbeam[tid]];
            sops[1 - cur][t][tid] = nop[tid];
        }
        __syncthreads();
        cur ^= 1;
        // hr = tanh(hr_sel @ Whh + exh[op] + bh) : warp w -> beams {2w,2w+1}, float4 cols
        if (warp < 4) {
            int r0 = warp * 2, r1 = r0 + 1;
            const float* h0 = shr[1] + r0 * 128;
            const float* h1 = shr[1] + r1 * 128;
            float4 a0 = make_float4(0.f, 0.f, 0.f, 0.f);
            float4 a1 = make_float4(0.f, 0.f, 0.f, 0.f);
            #pragma unroll 4
            for (int d = 0; d < 128; d++) {
                float4 w4 = *(const float4*)(Whh + d * 128 + 4 * lane);
                float v0 = h0[d], v1 = h1[d];
                a0.x += v0 * w4.x; a0.y += v0 * w4.y; a0.z += v0 * w4.z; a0.w += v0 * w4.w;
                a1.x += v1 * w4.x; a1.y += v1 * w4.y; a1.z += v1 * w4.z; a1.w += v1 * w4.w;
            }
            int j = 4 * lane;
            int o0 = nop[r0], o1 = nop[r1];
            const float* e0 = sexh + o0 * 128;
            const float* e1 = sexh + o1 * 128;
            float* d0 = shr[0] + r0 * 128;
            float* d1 = shr[0] + r1 * 128;
            d0[j + 0] = tanhf(a0.x + e0[j + 0] + sbh[j + 0]);
            d0[j + 1] = tanhf(a0.y + e0[j + 1] + sbh[j + 1]);
            d0[j + 2] = tanhf(a0.z + e0[j + 2] + sbh[j + 2]);
            d0[j + 3] = tanhf(a0.w + e0[j + 3] + sbh[j + 3]);
            d1[j + 0] = tanhf(a1.x + e1[j + 0] + sbh[j + 0]);
            d1[j + 1] = tanhf(a1.y + e1[j + 1] + sbh[j + 1]);
            d1[j + 2] = tanhf(a1.z + e1[j + 2] + sbh[j + 2]);
            d1[j + 3] = tanhf(a1.w + e1[j + 3] + sbh[j + 3]);
        }
        __syncthreads();
    }

    // ---- expert chain: warp w == beam w ----
    {
        int j = 4 * lane;
        hbuf[warp][j + 0] = sfeat[j + 0];
        hbuf[warp][j + 1] = sfeat[j + 1];
        hbuf[warp][j + 2] = sfeat[j + 2];
        hbuf[warp][j + 3] = sfeat[j + 3];
        __syncwarp();
        const float* hh = hbuf[warp];
        #pragma unroll
        for (int t = 0; t < 3; t++) {
            int o = sops[cur][t][warp];
            const float* W = Wexp + o * 16384;
            float4 acc = *(const float4*)(bexp + o * 128 + j);
            #pragma unroll 4
            for (int d = 0; d < 128; d++) {
                float hv = hh[d];
                float4 w4 = *(const float4*)(W + d * 128 + j);
                acc.x += hv * w4.x; acc.y += hv * w4.y;
                acc.z += hv * w4.z; acc.w += hv * w4.w;
            }
            __syncwarp();
            hbuf[warp][j + 0] = fmaxf(acc.x, 0.f);
            hbuf[warp][j + 1] = fmaxf(acc.y, 0.f);
            hbuf[warp][j + 2] = fmaxf(acc.z, 0.f);
            hbuf[warp][j + 3] = fmaxf(acc.w, 0.f);
            __syncwarp();
        }
        // final 128->10 + log_softmax (half-warp shuffle reduce)
        float logit = NEG;
        if (lane < 10) {
            float acc = bout[lane];
            #pragma unroll 4
            for (int d = 0; d < 128; d++) acc += hh[d] * Wout[d * 10 + lane];
            logit = acc;
        }
        float mx = logit;
        #pragma unroll
        for (int off = 8; off; off >>= 1)
            mx = fmaxf(mx, __shfl_xor_sync(0xffffffffu, mx, off, 16));
        float p = (lane < 10) ? expf(logit - mx) : 0.f;
        float s = p;
        #pragma unroll
        for (int off = 8; off; off >>= 1)
            s += __shfl_xor_sync(0xffffffffu, s, off, 16);
        if (lane < 10) out[(b * 8 + warp) * 10 + lane] = logit - mx - logf(s);
    }
}

// ---------------- launcher ----------------
extern "C" void kernel_launch(void* const* d_in, const int* in_sizes, int n_in,
                              void* d_out, int out_size)
{
    const float* x       = (const float*)d_in[0];
    const float* conv1_w = (const float*)d_in[1];
    const float* conv1_b = (const float*)d_in[2];
    const float* bn1_g   = (const float*)d_in[3];
    const float* bn1_b   = (const float*)d_in[4];
    const float* bn1_m   = (const float*)d_in[5];
    const float* bn1_v   = (const float*)d_in[6];
    const float* conv2_w = (const float*)d_in[7];
    const float* conv2_b = (const float*)d_in[8];
    const float* bn2_g   = (const float*)d_in[9];
    const float* bn2_b   = (const float*)d_in[10];
    const float* bn2_m   = (const float*)d_in[11];
    const float* bn2_v   = (const float*)d_in[12];
    const float* conv3_w = (const float*)d_in[13];
    const float* conv3_b = (const float*)d_in[14];
    const float* bn3_g   = (const float*)d_in[15];
    const float* bn3_b   = (const float*)d_in[16];
    const float* bn3_m   = (const float*)d_in[17];
    const float* bn3_v   = (const float*)d_in[18];
    const float* Wxh     = (const float*)d_in[19];
    const float* Whh     = (const float*)d_in[20];
    const float* bh      = (const float*)d_in[21];
    const float* Who     = (const float*)d_in[22];
    const float* bo      = (const float*)d_in[23];
    const float* emb     = (const float*)d_in[24];
    const float* Wexp    = (const float*)d_in[25];
    const float* bexp    = (const float*)d_in[26];
    const float* Wout    = (const float*)d_in[27];
    const float* bout    = (const float*)d_in[28];
    float* out = (float*)d_out;

    cudaFuncSetAttribute(k_conv_all, cudaFuncAttributeMaxDynamicSharedMemorySize, 81920);

    k_conv_all<<<BATCH, 288, 81920>>>(x,
        conv1_w, conv1_b, bn1_g, bn1_b, bn1_m, bn1_v,
        conv2_w, conv2_b, bn2_g, bn2_b, bn2_m, bn2_v,
        conv3_w, conv3_b, bn3_g, bn3_b, bn3_m, bn3_v);
    k_router<<<BATCH, 256>>>(Whh, bh, Who, bo, emb, Wxh,
                             Wexp, bexp, Wout, bout, out);
}